// round 5
// baseline (speedup 1.0000x reference)
#include <cuda_runtime.h>
#include <math.h>

// YearOperatorRouter: per-sample routed 3x3 edge magnitude.
// kx = [[-p,0,p],[-q,0,q],[-p,0,p]], ky = kx^T; out = sqrt(gx^2+gy^2+eps)*s, zero pad.
//
// One warp spans a full 256-px row (8 px/lane, two float4 loads). Horizontal
// halos come from neighbor lanes via shuffle -> zero scalar loads. 8 output
// rows per thread with a rolling 3-row register window.

#define W 256
#define H 256
#define RPT 8   // output rows per thread

struct Row10 { float v[10]; };

__device__ __forceinline__ void load_row10(const float* __restrict__ row, int x0,
                                           int lane, float r[10]) {
    float4 m0 = __ldg(reinterpret_cast<const float4*>(row + x0));
    float4 m1 = __ldg(reinterpret_cast<const float4*>(row + x0 + 4));
    float L = __shfl_up_sync(0xffffffffu, m1.w, 1);    // lane-1's x0+7 == my x0-1
    float R = __shfl_down_sync(0xffffffffu, m0.x, 1);  // lane+1's x0   == my x0+8
    if (lane == 0)  L = 0.0f;   // image left edge
    if (lane == 31) R = 0.0f;   // image right edge
    r[0] = L;
    r[1] = m0.x; r[2] = m0.y; r[3] = m0.z; r[4] = m0.w;
    r[5] = m1.x; r[6] = m1.y; r[7] = m1.z; r[8] = m1.w;
    r[9] = R;
}

__device__ __forceinline__ void zero_row10(float r[10]) {
#pragma unroll
    for (int j = 0; j < 10; j++) r[j] = 0.0f;
}

__global__ __launch_bounds__(128)
void year_router_kernel(const float* __restrict__ x,
                        const float* __restrict__ alpha,
                        const float* __restrict__ scale,
                        const int*   __restrict__ year,
                        float* __restrict__ out,
                        int C)
{
    const int lane = threadIdx.x;                 // blockDim.x == 32
    const int x0   = lane * 8;                    // 0..248
    const int y0   = (blockIdx.y * blockDim.y + threadIdx.y) * RPT;
    const int bc   = blockIdx.z;
    const int b    = bc / C;

    // ---- per-sample operator parameters (uniform per z-block) ----
    const int yr = __ldg(year + b);
    float p, q, eps, s;
    if (yr == 2019) {            // sobel
        p = 1.0f; q = 2.0f; eps = 1e-8f; s = 1.0f;
    } else if (yr == 2020) {     // scharr
        p = 3.0f; q = 10.0f; eps = 1e-8f; s = 1.0f;
    } else {                     // learnable: sigmoid mix, normalized by max|k| (= q term)
        float a  = 1.0f / (1.0f + expf(-__ldg(alpha)));
        float pm = 3.0f  - 2.0f * a;
        float qm = 10.0f - 8.0f * a;    // qm > pm > 0 for a in (0,1)
        p = pm / qm; q = 1.0f;
        eps = 1e-6f;
        s = 1.0f / (1.0f + expf(-__ldg(scale)));
    }

    const float* __restrict__ base  = x   + (size_t)bc * H * W;
    float*       __restrict__ obase = out + (size_t)bc * H * W;

    // ---- rolling 3-row register window (all branches warp-uniform: y same per warp) ----
    float rows[3][10];
    if (y0 > 0) load_row10(base + (size_t)(y0 - 1) * W, x0, lane, rows[0]);
    else        zero_row10(rows[0]);
    load_row10(base + (size_t)y0 * W, x0, lane, rows[1]);

#pragma unroll
    for (int i = 0; i < RPT; i++) {
        const int yn = y0 + i + 1;
        float* rn = rows[(i + 2) % 3];
        if (yn < H) load_row10(base + (size_t)yn * W, x0, lane, rn);
        else        zero_row10(rn);

        const float* r0 = rows[(i + 0) % 3];   // y-1
        const float* r1 = rows[(i + 1) % 3];   // y
        const float* r2 = rn;                  // y+1

        // vertical diffs shared across adjacent output pixels
        float d[10];
#pragma unroll
        for (int j = 0; j < 10; j++) d[j] = r2[j] - r0[j];

        float o[8];
#pragma unroll
        for (int j = 0; j < 8; j++) {
            float gx = fmaf(q, r1[j + 2] - r1[j],
                            p * ((r0[j + 2] - r0[j]) + (r2[j + 2] - r2[j])));
            float gy = fmaf(q, d[j + 1], p * (d[j] + d[j + 2]));
            float g2 = fmaf(gx, gx, fmaf(gy, gy, eps));
            o[j] = g2 * __frsqrt_rn(g2) * s;   // sqrt(g2)*s, g2 >= eps > 0
        }
        float4* orow = reinterpret_cast<float4*>(obase + (size_t)(y0 + i) * W + x0);
        orow[0] = make_float4(o[0], o[1], o[2], o[3]);
        orow[1] = make_float4(o[4], o[5], o[6], o[7]);
    }
}

extern "C" void kernel_launch(void* const* d_in, const int* in_sizes, int n_in,
                              void* d_out, int out_size)
{
    const float* x     = (const float*)d_in[0];   // [B, C, 256, 256] f32
    const float* alpha = (const float*)d_in[1];   // scalar f32
    const float* scale = (const float*)d_in[2];   // [1] f32
    const int*   year  = (const int*)d_in[3];     // [B] int32
    float* out = (float*)d_out;

    const int B  = in_sizes[3];
    const int BC = in_sizes[0] / (H * W);
    const int C  = BC / B;

    dim3 block(32, 4, 1);                 // 1 warp per row-strip, 4 strips per block
    dim3 grid(1, H / (RPT * 4), BC);      // 8 y-blocks, BC z-blocks (2304 total)

    year_router_kernel<<<grid, block>>>(x, alpha, scale, year, out, C);
}